// round 4
// baseline (speedup 1.0000x reference)
#include <cuda_runtime.h>
#include <math.h>

#define BB 8
#define LL 2048
#define DD 128
#define NROWS 16384    // B*L
#define TOTROWS 32768  // cn rows then en rows

// -------- device scratch (static, allocation-free) --------
__device__ float4 g_norm4[TOTROWS * (DD / 4)];  // normalized rows; [0,16384)=cn, [16384,32768)=en
__device__ float  g_ent_t[BB * DD * LL];        // entity-major transpose: [b][k][l]
__device__ float  g_f[TOTROWS];                 // f(x) per normalized row
__device__ float4 g_W1t4[DD * (DD / 4)];        // W1^T : row j holds column j of W1

// ---- packed f32x2 helpers (sm_103a FFMA2 path) ----
__device__ __forceinline__ void ffma2(unsigned long long& acc,
                                      unsigned long long a, unsigned long long b) {
    asm("fma.rn.f32x2 %0, %1, %2, %0;" : "+l"(acc) : "l"(a), "l"(b));
}
__device__ __forceinline__ unsigned long long dup2(float x) {
    unsigned long long r;
    unsigned xi = __float_as_uint(x);
    asm("mov.b64 %0, {%1, %1};" : "=l"(r) : "r"(xi));
    return r;
}
__device__ __forceinline__ void unpack2(unsigned long long v, float& lo, float& hi) {
    unsigned a, b;
    asm("mov.b64 {%0, %1}, %2;" : "=r"(a), "=r"(b) : "l"(v));
    lo = __uint_as_float(a);
    hi = __uint_as_float(b);
}

// ============================================================
// Pass 1: L2-normalize both context slices into g_norm4
// ============================================================
__global__ void norm_kernel(const float* __restrict__ context) {
    int warpId = (blockIdx.x * blockDim.x + threadIdx.x) >> 5;
    int lane = threadIdx.x & 31;
    if (warpId >= TOTROWS) return;
    int s  = warpId >> 14;        // 0 = ctx, 1 = ent
    int bl = warpId & (NROWS - 1);
    int b = bl >> 11, l = bl & (LL - 1);
    const float4* src = reinterpret_cast<const float4*>(context)
                        + ((size_t)((b * 2 + s) * LL + l)) * (DD / 4);
    float4 v = src[lane];
    float ss = v.x * v.x + v.y * v.y + v.z * v.z + v.w * v.w;
    #pragma unroll
    for (int off = 16; off; off >>= 1) ss += __shfl_xor_sync(0xffffffffu, ss, off);
    float inv = 1.0f / fmaxf(sqrtf(ss), 1e-8f);
    float4 o = make_float4(v.x * inv, v.y * inv, v.z * inv, v.w * inv);
    g_norm4[(size_t)warpId * (DD / 4) + lane] = o;
}

// ============================================================
// Pass 2a: transpose W1 (tiny)
// ============================================================
__global__ void transpose_kernel(const float* __restrict__ W1) {
    int t = blockIdx.x * blockDim.x + threadIdx.x;
    if (t < DD * DD) {
        int k = t >> 7, j = t & 127;
        reinterpret_cast<float*>(g_W1t4)[j * DD + k] = W1[t];
    }
}

// ============================================================
// Pass 2b: entity rows -> entity-major [b][k][l] for packed-pair B loads
// ============================================================
__global__ void ent_transpose_kernel() {
    __shared__ float t[32][33];
    int b = blockIdx.z;
    int l0 = blockIdx.x * 32;
    int k0 = blockIdx.y * 32;
    const float* src = reinterpret_cast<const float*>(g_norm4)
                       + (size_t)(NROWS + b * LL) * DD;
    #pragma unroll
    for (int r = 0; r < 4; ++r) {
        int l = threadIdx.y + 8 * r;
        t[l][threadIdx.x] = src[(size_t)(l0 + l) * DD + k0 + threadIdx.x];
    }
    __syncthreads();
    float* dst = g_ent_t + (size_t)b * DD * LL;
    #pragma unroll
    for (int r = 0; r < 4; ++r) {
        int k = threadIdx.y + 8 * r;
        dst[(size_t)(k0 + k) * LL + l0 + threadIdx.x] = t[threadIdx.x][k];
    }
}

// Swizzled granule index: tile stored as [row][32 float4 granules],
// granule column XOR'd with low 5 bits of row -> conflict-free STS and LDS.
__device__ __forceinline__ int swz(int row, int k4) {
    return row * 32 + (k4 ^ (row & 31));
}

__device__ __forceinline__ unsigned smem_u32(const void* p) {
    return (unsigned)__cvta_generic_to_shared(p);
}

// Cooperative synchronous tile load: 128 rows x 32 float4 granules (stride 32).
__device__ __forceinline__ void load_tile(float4* dst, const float4* __restrict__ srcBase,
                                          int tid) {
    int w = tid >> 5, lane = tid & 31;
    #pragma unroll
    for (int r = w; r < 128; r += 8) {
        float4 v = srcBase[(size_t)r * 32 + lane];
        dst[swz(r, lane)] = v;
    }
}

// Async tile load with arbitrary source row stride (in float4 granules).
__device__ __forceinline__ void load_tile_async_strided(float4* dst,
                                                        const float4* __restrict__ srcBase,
                                                        size_t rowStride, int tid) {
    int w = tid >> 5, lane = tid & 31;
    #pragma unroll
    for (int r = w; r < 128; r += 8) {
        unsigned d = smem_u32(&dst[swz(r, lane)]);
        const float4* s = srcBase + (size_t)r * rowStride + lane;
        asm volatile("cp.async.cg.shared.global [%0], [%1], 16;\n" :: "r"(d), "l"(s));
    }
}

// ============================================================
// Pass 3: MLP f(x) for all 32768 rows.  X_tile(128x128) @ W1 (+b1, relu, @W2, +b2)
// ============================================================
__global__ __launch_bounds__(256, 1) void mlp_kernel(const float* __restrict__ b1,
                                                     const float* __restrict__ W2,
                                                     const float* __restrict__ b2) {
    extern __shared__ float4 sm[];
    float4* As = sm;              // 64 KB
    float4* Bs = sm + 128 * 32;   // 64 KB
    int tid = threadIdx.x;
    int tx = tid & 15, ty = tid >> 4;
    int rowBase = blockIdx.x * 128;

    load_tile(As, g_norm4 + (size_t)rowBase * 32, tid);
    load_tile(Bs, g_W1t4, tid);
    __syncthreads();

    float acc[8][8];
    #pragma unroll
    for (int i = 0; i < 8; ++i)
        #pragma unroll
        for (int j = 0; j < 8; ++j) acc[i][j] = 0.0f;

    #pragma unroll 2
    for (int k4 = 0; k4 < 32; ++k4) {
        float4 av[8], bv[8];
        #pragma unroll
        for (int i = 0; i < 8; ++i) av[i] = As[swz(ty + 16 * i, k4)];
        #pragma unroll
        for (int j = 0; j < 8; ++j) bv[j] = Bs[swz(tx + 16 * j, k4)];
        #pragma unroll
        for (int i = 0; i < 8; ++i)
            #pragma unroll
            for (int j = 0; j < 8; ++j) {
                float a = acc[i][j];
                a = fmaf(av[i].x, bv[j].x, a);
                a = fmaf(av[i].y, bv[j].y, a);
                a = fmaf(av[i].z, bv[j].z, a);
                a = fmaf(av[i].w, bv[j].w, a);
                acc[i][j] = a;
            }
    }

    // epilogue: relu(acc + b1) * W2, sum over hidden dim
    float b1r[8], w2r[8];
    #pragma unroll
    for (int j = 0; j < 8; ++j) {
        b1r[j] = b1[tx + 16 * j];
        w2r[j] = W2[tx + 16 * j];
    }
    float b2v = b2[0];
    #pragma unroll
    for (int i = 0; i < 8; ++i) {
        float p = 0.0f;
        #pragma unroll
        for (int j = 0; j < 8; ++j) {
            float h = fmaxf(acc[i][j] + b1r[j], 0.0f);
            p = fmaf(h, w2r[j], p);
        }
        #pragma unroll
        for (int off = 8; off; off >>= 1)
            p += __shfl_down_sync(0xffffffffu, p, off, 16);
        if (tx == 0) g_f[rowBase + ty + 16 * i] = p + b2v;
    }
}

// ============================================================
// Pass 4: per-batch cosine-sim argmax via packed f32x2 FMA.
// A tile: [row][k] (token-major, swizzled float4 granules).
// B tile: [k][entity] (entity-major, swizzled) -> entity pairs are LDS.64.
// acc2[i][jp] packs entities {2*(tx+16*jp), 2*(tx+16*jp)+1} for row ty+16*i.
// ============================================================
__global__ __launch_bounds__(256, 1) void argmax_kernel(float* __restrict__ out) {
    extern __shared__ float4 sm[];
    float4* As = sm;                       // 64 KB
    float4* Bs[2] = { sm + 128 * 32,       // 64 KB
                      sm + 2 * 128 * 32 }; // 64 KB
    int tid = threadIdx.x;
    int tx = tid & 15, ty = tid >> 4;
    int tx1 = tx >> 1;
    int h8 = (tx & 1) * 8;
    int b = blockIdx.y;
    int rowBase = b * LL + blockIdx.x * 128;              // global cn row
    const float4* entSrc = reinterpret_cast<const float4*>(g_ent_t + (size_t)b * DD * LL);
    const size_t entStride = LL / 4;                      // granules per k-row

    // async prologue: A tile + entity tile 0 in one group
    load_tile_async_strided(As, g_norm4 + (size_t)rowBase * 32, 32, tid);
    load_tile_async_strided(Bs[0], entSrc, entStride, tid);
    asm volatile("cp.async.commit_group;\n" ::);

    float bestV[8];
    int bestI[8];
    #pragma unroll
    for (int i = 0; i < 8; ++i) { bestV[i] = -1e30f; bestI[i] = 0; }

    for (int t = 0; t < 16; ++t) {
        int entBase = t * 128;
        __syncthreads();   // everyone done reading the buffer we are about to overwrite
        if (t + 1 < 16) {
            load_tile_async_strided(Bs[(t + 1) & 1], entSrc + (size_t)(t + 1) * 32,
                                    entStride, tid);
            asm volatile("cp.async.commit_group;\n" ::);
            asm volatile("cp.async.wait_group 1;\n" ::);
        } else {
            asm volatile("cp.async.wait_group 0;\n" ::);
        }
        __syncthreads();   // tile t (and A on t==0) visible
        const char* Bb = reinterpret_cast<const char*>(Bs[t & 1]);

        unsigned long long acc2[8][4];
        #pragma unroll
        for (int i = 0; i < 8; ++i)
            #pragma unroll
            for (int jp = 0; jp < 4; ++jp) acc2[i][jp] = 0ull;

        #pragma unroll 1          // body ~3 KB SASS; keep it resident in L0 I$
        for (int k4 = 0; k4 < 32; ++k4) {
            float4 av[8];
            #pragma unroll
            for (int i = 0; i < 8; ++i) av[i] = As[swz(ty + 16 * i, k4)];
            #pragma unroll
            for (int ke = 0; ke < 4; ++ke) {
                int k = 4 * k4 + ke;
                int kx = k & 31;
                unsigned long long bv[4];
                #pragma unroll
                for (int jp = 0; jp < 4; ++jp) {
                    int off = k * 512 + (((tx1 + 8 * jp) ^ kx) << 4) + h8;
                    bv[jp] = *reinterpret_cast<const unsigned long long*>(Bb + off);
                }
                #pragma unroll
                for (int i = 0; i < 8; ++i) {
                    float a_s = (ke == 0) ? av[i].x : (ke == 1) ? av[i].y
                              : (ke == 2) ? av[i].z : av[i].w;
                    unsigned long long ad = dup2(a_s);
                    #pragma unroll
                    for (int jp = 0; jp < 4; ++jp) ffma2(acc2[i][jp], ad, bv[jp]);
                }
            }
        }

        // running argmax update (comparator is index-aware -> order-robust)
        #pragma unroll
        for (int i = 0; i < 8; ++i)
            #pragma unroll
            for (int jp = 0; jp < 4; ++jp) {
                float lo, hi;
                unpack2(acc2[i][jp], lo, hi);
                int e0 = entBase + 2 * (tx + 16 * jp);
                if (lo > bestV[i] || (lo == bestV[i] && e0 < bestI[i])) {
                    bestV[i] = lo; bestI[i] = e0;
                }
                int e1 = e0 + 1;
                if (hi > bestV[i] || (hi == bestV[i] && e1 < bestI[i])) {
                    bestV[i] = hi; bestI[i] = e1;
                }
            }
    }

    // reduce across the 16 tx lanes sharing each row; lower index wins ties
    #pragma unroll
    for (int i = 0; i < 8; ++i) {
        float v = bestV[i];
        int e = bestI[i];
        #pragma unroll
        for (int off = 8; off; off >>= 1) {
            float ov = __shfl_down_sync(0xffffffffu, v, off, 16);
            int oe = __shfl_down_sync(0xffffffffu, e, off, 16);
            if (ov > v || (ov == v && oe < e)) { v = ov; e = oe; }
        }
        if (tx == 0) {
            int row = blockIdx.x * 128 + ty + 16 * i;
            float f1 = g_f[b * LL + row];           // f(cn)
            float f2 = g_f[NROWS + b * LL + e];     // f(matched en)
            out[b * LL + row] = f1 + f2;
        }
    }
}

// ============================================================
extern "C" void kernel_launch(void* const* d_in, const int* in_sizes, int n_in,
                              void* d_out, int out_size) {
    const float* context = (const float*)d_in[0];
    const float* W1 = (const float*)d_in[1];
    const float* b1 = (const float*)d_in[2];
    const float* W2 = (const float*)d_in[3];
    const float* b2 = (const float*)d_in[4];
    float* out = (float*)d_out;

    const int SMEM_MLP = 128 * 1024;   // As + Bs
    const int SMEM_AM  = 192 * 1024;   // As + 2x Bs (double buffer)
    cudaFuncSetAttribute(mlp_kernel, cudaFuncAttributeMaxDynamicSharedMemorySize, SMEM_MLP);
    cudaFuncSetAttribute(argmax_kernel, cudaFuncAttributeMaxDynamicSharedMemorySize, SMEM_AM);

    norm_kernel<<<TOTROWS / 8, 256>>>(context);           // 8 warps/block
    transpose_kernel<<<(DD * DD + 255) / 256, 256>>>(W1);
    {
        dim3 gt(LL / 32, DD / 32, BB);
        dim3 bt(32, 8);
        ent_transpose_kernel<<<gt, bt>>>();
    }
    mlp_kernel<<<TOTROWS / 128, 256, SMEM_MLP>>>(b1, W2, b2);
    dim3 g(LL / 128, BB);
    argmax_kernel<<<g, 256, SMEM_AM>>>(out);
}

// round 10
// speedup vs baseline: 1.0460x; 1.0460x over previous
#include <cuda_runtime.h>
#include <cuda_bf16.h>
#include <math.h>
#include <stdint.h>

#define BB 8
#define LL 2048
#define DD 128
#define NROWS 16384    // B*L
#define TOTROWS 32768  // cn rows then en rows

// -------- device scratch (static, allocation-free) --------
__device__ float4 g_norm4[TOTROWS * (DD / 4)];          // normalized rows fp32
__device__ __nv_bfloat16 g_bh[TOTROWS * DD];            // bf16 hi of normalized rows
__device__ __nv_bfloat16 g_bl[TOTROWS * DD];            // bf16 lo (residual)
__device__ float  g_f[TOTROWS];                         // f(x) per normalized row
__device__ float4 g_W1t4[DD * (DD / 4)];                // W1^T
__device__ int    g_amax[NROWS];                        // approx argmax per cn row
__device__ int    g_flag[NROWS];                        // 1 = needs exact rescore

__device__ __forceinline__ uint32_t smem_u32(const void* p) {
    return (uint32_t)__cvta_generic_to_shared(p);
}

// ============================================================
// Pass 1: L2-normalize; also emit bf16 hi/lo split
// ============================================================
__global__ void norm_kernel(const float* __restrict__ context) {
    int warpId = (blockIdx.x * blockDim.x + threadIdx.x) >> 5;
    int lane = threadIdx.x & 31;
    if (warpId >= TOTROWS) return;
    int s  = warpId >> 14;
    int bl = warpId & (NROWS - 1);
    int b = bl >> 11, l = bl & (LL - 1);
    const float4* src = reinterpret_cast<const float4*>(context)
                        + ((size_t)((b * 2 + s) * LL + l)) * (DD / 4);
    float4 v = src[lane];
    float ss = v.x * v.x + v.y * v.y + v.z * v.z + v.w * v.w;
    #pragma unroll
    for (int off = 16; off; off >>= 1) ss += __shfl_xor_sync(0xffffffffu, ss, off);
    float inv = 1.0f / fmaxf(sqrtf(ss), 1e-8f);
    float4 o = make_float4(v.x * inv, v.y * inv, v.z * inv, v.w * inv);
    g_norm4[(size_t)warpId * (DD / 4) + lane] = o;

    __nv_bfloat16 hx = __float2bfloat16(o.x), hy = __float2bfloat16(o.y);
    __nv_bfloat16 hz = __float2bfloat16(o.z), hw = __float2bfloat16(o.w);
    __nv_bfloat16 lx = __float2bfloat16(o.x - __bfloat162float(hx));
    __nv_bfloat16 ly = __float2bfloat16(o.y - __bfloat162float(hy));
    __nv_bfloat16 lz = __float2bfloat16(o.z - __bfloat162float(hz));
    __nv_bfloat16 lw = __float2bfloat16(o.w - __bfloat162float(hw));
    __nv_bfloat162* ph = reinterpret_cast<__nv_bfloat162*>(g_bh + (size_t)warpId * DD);
    __nv_bfloat162* pl = reinterpret_cast<__nv_bfloat162*>(g_bl + (size_t)warpId * DD);
    ph[lane * 2 + 0] = __nv_bfloat162{hx, hy};
    ph[lane * 2 + 1] = __nv_bfloat162{hz, hw};
    pl[lane * 2 + 0] = __nv_bfloat162{lx, ly};
    pl[lane * 2 + 1] = __nv_bfloat162{lz, lw};
}

// ============================================================
// Pass 2: transpose W1 (tiny)
// ============================================================
__global__ void transpose_kernel(const float* __restrict__ W1) {
    int t = blockIdx.x * blockDim.x + threadIdx.x;
    if (t < DD * DD) {
        int k = t >> 7, j = t & 127;
        reinterpret_cast<float*>(g_W1t4)[j * DD + k] = W1[t];
    }
}

// ---- fp32 tile helpers for the MLP kernel ----
__device__ __forceinline__ int swz(int row, int k4) {
    return row * 32 + (k4 ^ (row & 31));
}
__device__ __forceinline__ void load_tile(float4* dst, const float4* __restrict__ srcBase,
                                          int tid) {
    int w = tid >> 5, lane = tid & 31;
    #pragma unroll
    for (int r = w; r < 128; r += 8) {
        float4 v = srcBase[(size_t)r * 32 + lane];
        dst[swz(r, lane)] = v;
    }
}

// ============================================================
// Pass 3: MLP f(x) for all 32768 rows (fp32, exact)
// ============================================================
__global__ __launch_bounds__(256, 1) void mlp_kernel(const float* __restrict__ b1,
                                                     const float* __restrict__ W2,
                                                     const float* __restrict__ b2) {
    extern __shared__ float4 sm[];
    float4* As = sm;
    float4* Bs = sm + 128 * 32;
    int tid = threadIdx.x;
    int tx = tid & 15, ty = tid >> 4;
    int rowBase = blockIdx.x * 128;

    load_tile(As, g_norm4 + (size_t)rowBase * 32, tid);
    load_tile(Bs, g_W1t4, tid);
    __syncthreads();

    float acc[8][8];
    #pragma unroll
    for (int i = 0; i < 8; ++i)
        #pragma unroll
        for (int j = 0; j < 8; ++j) acc[i][j] = 0.0f;

    #pragma unroll 2
    for (int k4 = 0; k4 < 32; ++k4) {
        float4 av[8], bv[8];
        #pragma unroll
        for (int i = 0; i < 8; ++i) av[i] = As[swz(ty + 16 * i, k4)];
        #pragma unroll
        for (int j = 0; j < 8; ++j) bv[j] = Bs[swz(tx + 16 * j, k4)];
        #pragma unroll
        for (int i = 0; i < 8; ++i)
            #pragma unroll
            for (int j = 0; j < 8; ++j) {
                float a = acc[i][j];
                a = fmaf(av[i].x, bv[j].x, a);
                a = fmaf(av[i].y, bv[j].y, a);
                a = fmaf(av[i].z, bv[j].z, a);
                a = fmaf(av[i].w, bv[j].w, a);
                acc[i][j] = a;
            }
    }

    float b1r[8], w2r[8];
    #pragma unroll
    for (int j = 0; j < 8; ++j) {
        b1r[j] = b1[tx + 16 * j];
        w2r[j] = W2[tx + 16 * j];
    }
    float b2v = b2[0];
    #pragma unroll
    for (int i = 0; i < 8; ++i) {
        float p = 0.0f;
        #pragma unroll
        for (int j = 0; j < 8; ++j) {
            float h = fmaxf(acc[i][j] + b1r[j], 0.0f);
            p = fmaf(h, w2r[j], p);
        }
        #pragma unroll
        for (int off = 8; off; off >>= 1)
            p += __shfl_down_sync(0xffffffffu, p, off, 16);
        if (tx == 0) g_f[rowBase + ty + 16 * i] = p + b2v;
    }
}

// ============================================================
// Pass 4: mma.sync split-bf16 sim + approx argmax with certainty gap.
// CTA 256 thr (8 warps: wm=wid&3 m-strips of 32, wn=wid>>2 n-strips of 64).
// M=128 cn rows; 16 N-tiles of 128 entities; K=128 (8 k-steps x 3 passes).
// ============================================================
#define TSTRIDE 272                    // smem bytes per tile row (17 granules, 17 % 8 == 1)
#define TILEB   (128 * TSTRIDE)        // 34816 per tile
#define O_AH    0
#define O_AL    (TILEB)
#define O_BH0   (2 * TILEB)
#define O_BL0   (3 * TILEB)
#define O_BH1   (4 * TILEB)
#define O_BL1   (5 * TILEB)
#define SM_SIM_TOTAL (6 * TILEB)       // 208896 bytes

#define SIM_THRESH 1e-4f

__device__ __forceinline__ void ldmx4(uint32_t* r, uint32_t addr) {
    asm volatile("ldmatrix.sync.aligned.m8n8.x4.shared.b16 {%0,%1,%2,%3}, [%4];"
                 : "=r"(r[0]), "=r"(r[1]), "=r"(r[2]), "=r"(r[3]) : "r"(addr));
}
__device__ __forceinline__ void mma16816(float* d, const uint32_t* a, const uint32_t* b) {
    asm volatile(
        "mma.sync.aligned.m16n8k16.row.col.f32.bf16.bf16.f32 "
        "{%0,%1,%2,%3}, {%4,%5,%6,%7}, {%8,%9}, {%0,%1,%2,%3};"
        : "+f"(d[0]), "+f"(d[1]), "+f"(d[2]), "+f"(d[3])
        : "r"(a[0]), "r"(a[1]), "r"(a[2]), "r"(a[3]), "r"(b[0]), "r"(b[1]));
}

// async copy one 128x128 bf16 tile (row-major) into smem with 272B row stride
__device__ __forceinline__ void sim_load_tile(uint32_t dst, const __nv_bfloat16* __restrict__ src,
                                              int tid) {
    #pragma unroll
    for (int it = 0; it < 8; ++it) {
        int i = tid + it * 256;
        int r = i >> 4, g = i & 15;
        uint32_t d = dst + r * TSTRIDE + g * 16;
        const __nv_bfloat16* s = src + (size_t)r * DD + g * 8;
        asm volatile("cp.async.cg.shared.global [%0], [%1], 16;\n" :: "r"(d), "l"(s));
    }
}

__global__ __launch_bounds__(256, 1) void sim_argmax_kernel() {
    extern __shared__ char smc[];
    uint32_t sb = smem_u32(smc);
    int tid = threadIdx.x, lane = tid & 31, wid = tid >> 5;
    int wm = wid & 3, wn = wid >> 2;
    int mt128 = blockIdx.x, b = blockIdx.y;
    int rowBase = b * LL + mt128 * 128;                 // global cn row of tile row 0
    const __nv_bfloat16* enh = g_bh + (size_t)(NROWS + b * LL) * DD;
    const __nv_bfloat16* enl = g_bl + (size_t)(NROWS + b * LL) * DD;

    // prologue: A (hi+lo) + entity tile 0 (hi+lo), one group
    sim_load_tile(sb + O_AH, g_bh + (size_t)rowBase * DD, tid);
    sim_load_tile(sb + O_AL, g_bl + (size_t)rowBase * DD, tid);
    sim_load_tile(sb + O_BH0, enh, tid);
    sim_load_tile(sb + O_BL0, enl, tid);
    asm volatile("cp.async.commit_group;\n" ::);

    const uint32_t bhOff[2] = { O_BH0, O_BH1 };
    const uint32_t blOff[2] = { O_BL0, O_BL1 };

    // per-lane running best/second for 4 row-entries: e = mt*2 + (dreg>>1)
    float best[4], sec[4];
    int bidx[4];
    #pragma unroll
    for (int e = 0; e < 4; ++e) { best[e] = -3e38f; sec[e] = -3e38f; bidx[e] = 0; }

    // precomputed ldmatrix base addresses (lane-dependent parts)
    int a_row = wm * 32 + (lane & 15);          // + mt*16
    int a_kg = lane >> 4;
    int b_row = wn * 64 + ((lane >> 4) << 3) + (lane & 7);  // + np*16
    int b_kg = (lane >> 3) & 1;

    #pragma unroll 1
    for (int t = 0; t < 16; ++t) {
        if (t + 1 < 16) {
            sim_load_tile(sb + bhOff[(t + 1) & 1], enh + (size_t)(t + 1) * 128 * DD, tid);
            sim_load_tile(sb + blOff[(t + 1) & 1], enl + (size_t)(t + 1) * 128 * DD, tid);
            asm volatile("cp.async.commit_group;\n" ::);
            asm volatile("cp.async.wait_group 1;\n" ::);
        } else {
            asm volatile("cp.async.wait_group 0;\n" ::);
        }
        __syncthreads();                       // tile t visible to all threads

        float acc[2][8][4];
        #pragma unroll
        for (int mt = 0; mt < 2; ++mt)
            #pragma unroll
            for (int nt = 0; nt < 8; ++nt)
                #pragma unroll
                for (int d = 0; d < 4; ++d) acc[mt][nt][d] = 0.0f;

        #pragma unroll
        for (int p = 0; p < 3; ++p) {
            uint32_t Ab = sb + (p == 2 ? O_AL : O_AH);
            uint32_t Bb = sb + (p == 1 ? blOff[t & 1] : bhOff[t & 1]);
            #pragma unroll
            for (int ks = 0; ks < 8; ++ks) {
                uint32_t bf[4][4];
                #pragma unroll
                for (int np = 0; np < 4; ++np) {
                    uint32_t addr = Bb + (b_row + np * 16) * TSTRIDE + (ks * 2 + b_kg) * 16;
                    ldmx4(bf[np], addr);
                }
                #pragma unroll
                for (int mt = 0; mt < 2; ++mt) {
                    uint32_t af[4];
                    uint32_t addr = Ab + (a_row + mt * 16) * TSTRIDE + (ks * 2 + a_kg) * 16;
                    ldmx4(af, addr);
                    #pragma unroll
                    for (int np = 0; np < 4; ++np) {
                        mma16816(acc[mt][2 * np + 0], af, &bf[np][0]);
                        mma16816(acc[mt][2 * np + 1], af, &bf[np][2]);
                    }
                }
            }
        }
        __syncthreads();                       // all reads done before next prefetch overwrites

        // running argmax update
        #pragma unroll
        for (int mt = 0; mt < 2; ++mt)
            #pragma unroll
            for (int nt = 0; nt < 8; ++nt)
                #pragma unroll
                for (int d = 0; d < 4; ++d) {
                    float v = acc[mt][nt][d];
                    int e = mt * 2 + (d >> 1);
                    int n = t * 128 + wn * 64 + nt * 8 + (lane & 3) * 2 + (d & 1);
                    if (v > best[e]) { sec[e] = best[e]; best[e] = v; bidx[e] = n; }
                    else if (v > sec[e]) sec[e] = v;   // v==best -> sec=best -> gap 0 -> rescore
                }
    }

    // intra-warp: merge across the 4 lanes sharing each row (lane groups of 4)
    #pragma unroll
    for (int e = 0; e < 4; ++e) {
        #pragma unroll
        for (int off = 1; off <= 2; off <<= 1) {
            float ob = __shfl_xor_sync(0xffffffffu, best[e], off);
            float os = __shfl_xor_sync(0xffffffffu, sec[e], off);
            int oi = __shfl_xor_sync(0xffffffffu, bidx[e], off);
            if (ob > best[e] || (ob == best[e] && oi < bidx[e])) {
                sec[e] = fmaxf(best[e], os);
                best[e] = ob; bidx[e] = oi;
            } else {
                sec[e] = fmaxf(sec[e], ob);
            }
        }
    }

    // cross-warp combine: overlay reduction arrays on tile smem (done with tiles)
    __syncthreads();
    float* sbest = reinterpret_cast<float*>(smc);          // [2][128]
    float* ssec  = sbest + 256;
    int*   sidx  = reinterpret_cast<int*>(ssec + 256);
    if ((lane & 3) == 0) {
        #pragma unroll
        for (int e = 0; e < 4; ++e) {
            int row = wm * 32 + (e >> 1) * 16 + (lane >> 2) + (e & 1) * 8;
            sbest[wn * 128 + row] = best[e];
            ssec[wn * 128 + row]  = sec[e];
            sidx[wn * 128 + row]  = bidx[e];
        }
    }
    __syncthreads();
    if (tid < 128) {
        float b0 = sbest[tid], s0 = ssec[tid];
        int i0 = sidx[tid];
        float b1v = sbest[128 + tid], s1 = ssec[128 + tid];
        int i1 = sidx[128 + tid];
        float fb, fs; int fi;
        if (b1v > b0 || (b1v == b0 && i1 < i0)) {
            fb = b1v; fi = i1; fs = fmaxf(b0, s1);
        } else {
            fb = b0; fi = i0; fs = fmaxf(s0, b1v);
        }
        g_amax[rowBase + tid] = fi;
        g_flag[rowBase + tid] = (fb - fs < SIM_THRESH) ? 1 : 0;
    }
}

// ============================================================
// Pass 5: finalize — exact-fp32 rescore for flagged rows, gather f, write out.
// One warp per cn row.
// ============================================================
__global__ __launch_bounds__(256) void finalize_kernel(float* __restrict__ out) {
    __shared__ float4 s_cn[8][32];
    int gw = (blockIdx.x * blockDim.x + threadIdx.x) >> 5;  // global cn row
    int lane = threadIdx.x & 31;
    int wloc = (threadIdx.x >> 5);
    if (gw >= NROWS) return;
    int b = gw >> 11;
    int idx;
    if (!g_flag[gw]) {
        idx = g_amax[gw];
    } else {
        s_cn[wloc][lane] = g_norm4[(size_t)gw * 32 + lane];
        __syncwarp();
        float bv = -3e38f; int bi = 0;
        for (int e = lane; e < LL; e += 32) {
            const float4* en = g_norm4 + (size_t)(NROWS + b * LL + e) * 32;
            float s = 0.0f;
            #pragma unroll
            for (int j = 0; j < 32; ++j) {
                float4 a = s_cn[wloc][j];
                float4 w = en[j];
                s = fmaf(a.x, w.x, s);
                s = fmaf(a.y, w.y, s);
                s = fmaf(a.z, w.z, s);
                s = fmaf(a.w, w.w, s);
            }
            if (s > bv || (s == bv && e < bi)) { bv = s; bi = e; }
        }
        #pragma unroll
        for (int off = 16; off; off >>= 1) {
            float ov = __shfl_down_sync(0xffffffffu, bv, off);
            int oi = __shfl_down_sync(0xffffffffu, bi, off);
            if (ov > bv || (ov == bv && oi < bi)) { bv = ov; bi = oi; }
        }
        idx = __shfl_sync(0xffffffffu, bi, 0);
    }
    if (lane == 0)
        out[gw] = g_f[gw] + g_f[NROWS + b * LL + idx];
}

// ============================================================
extern "C" void kernel_launch(void* const* d_in, const int* in_sizes, int n_in,
                              void* d_out, int out_size) {
    const float* context = (const float*)d_in[0];
    const float* W1 = (const float*)d_in[1];
    const float* b1 = (const float*)d_in[2];
    const float* W2 = (const float*)d_in[3];
    const float* b2 = (const float*)d_in[4];
    float* out = (float*)d_out;

    const int SMEM_MLP = 128 * 1024;
    cudaFuncSetAttribute(mlp_kernel, cudaFuncAttributeMaxDynamicSharedMemorySize, SMEM_MLP);
    cudaFuncSetAttribute(sim_argmax_kernel, cudaFuncAttributeMaxDynamicSharedMemorySize,
                         SM_SIM_TOTAL);

    norm_kernel<<<TOTROWS / 8, 256>>>(context);
    transpose_kernel<<<(DD * DD + 255) / 256, 256>>>(W1);
    mlp_kernel<<<TOTROWS / 128, 256, SMEM_MLP>>>(b1, W2, b2);
    dim3 g(LL / 128, BB);
    sim_argmax_kernel<<<g, 256, SM_SIM_TOTAL>>>();
    finalize_kernel<<<NROWS / 8, 256>>>(out);
}